// round 3
// baseline (speedup 1.0000x reference)
#include <cuda_runtime.h>
#include <cuda_bf16.h>

#define T_DIM 512
#define B_DIM 128
#define E_DIM 256
#define KMAX  512

// Compact band storage: coeff for slot (t - k) at g_bc[t][b][k], count g_nb[t][b].
__device__ float g_bc[(size_t)T_DIM * B_DIM * KMAX];
__device__ int   g_nb[T_DIM * B_DIM];

// ---------------------------------------------------------------------------
// Kernel A: one warp per batch. Lane i holds P(i) = inclusive prefix-from-top
// of stack strengths at depth i. Per step:
//   P_t(i) = d_t + relu(P_{t-1}(i-1) - u_t)     (pop eats from the top)
// Strengths at depth >= 32 spill to smem (sS, indexed by slot); Bm tracks
// their total mass. Deep pops / deep bands take rare uniform serial walks.
// ---------------------------------------------------------------------------
__global__ __launch_bounds__(32, 1) void scan_kernel(
    const float* __restrict__ u, const float* __restrict__ d) {
  const int b    = blockIdx.x;
  const int lane = threadIdx.x;

  __shared__ float su[T_DIM];
  __shared__ float sd[T_DIM];
  __shared__ float sS[T_DIM];   // spilled strengths, indexed by slot

  for (int j = lane; j < T_DIM; j += 32) {
    su[j] = u[j * B_DIM + b];
    sd[j] = d[j * B_DIM + b];
    sS[j] = 0.f;
  }
  __syncwarp();

  float P  = 0.f;   // P_{t-1}(lane)
  float Bm = 0.f;   // below-window mass (warp-uniform)

  for (int t = 0; t < T_DIM; ++t) {
    const float ut = su[t];
    const float dt = sd[t];

    // All shfls read P_{t-1}: independent, one shfl latency on the chain.
    float Pm1 = __shfl_up_sync(0xffffffffu, P, 1);
    float Pm2 = __shfl_up_sync(0xffffffffu, P, 2);
    float P31 = __shfl_sync(0xffffffffu, P, 31);
    float P30 = __shfl_sync(0xffffffffu, P, 30);
    if (lane == 0) Pm1 = 0.f;

    // New prefixes
    float Pn = dt + fmaxf(Pm1 - ut, 0.f);                 // P_t(lane)
    float Pnm1;                                           // P_t(lane-1)
    if      (lane == 0) Pnm1 = 0.f;
    else if (lane == 1) Pnm1 = dt;
    else                Pnm1 = dt + fmaxf(Pm2 - ut, 0.f);

    float S     = Pn - Pnm1;                              // strength (>= 0)
    float coeff = fminf(S, fmaxf(1.f - Pnm1, 0.f));

    // Band = contiguous lane prefix with used (=Pnm1) < 1 (used is monotone).
    unsigned bm = __ballot_sync(0xffffffffu, Pnm1 < 1.f);
    int nb = __popc(bm);
    if (nb > t + 1) nb = t + 1;                           // stack has t+1 slots

    float* bcrow = &g_bc[((size_t)t * B_DIM + b) * KMAX];
    if (lane < nb) bcrow[lane] = coeff;

    // ---- below-window bookkeeping (all values warp-uniform) ----
    float q31 = fmaxf(P31 - ut, 0.f);                     // post-pop prefixes
    float q30 = fmaxf(P30 - ut, 0.f);
    float Sexit = q31 - q30;              // strength of slot t-32 after pop
    float pop_below = fminf(Bm, fmaxf(ut - P31, 0.f));

    if (pop_below > 1e-7f) {              // rare: pop reaches spilled entries
      __syncwarp();
      float rem = pop_below;
      for (int s = t - 33; s >= 0; --s) {
        float Ss = sS[s];
        if (Ss > 0.f) {
          float c = fminf(Ss, rem);
          rem -= c;
          if (lane == 0) sS[s] = Ss - c;
          if (rem <= 0.f) break;
        }
      }
      __syncwarp();
    }
    Bm = fmaxf(Bm - pop_below, 0.f) + Sexit;
    if (lane == 0 && t >= 32) sS[t - 32] = Sexit;

    float Pn31 = dt + q30;                                // P_t(31)
    if (Pn31 < 1.f && Bm > 1e-6f && t >= 32) {            // rare: deep band
      __syncwarp();
      float cum = Pn31;
      int k = 32;
      for (int s = t - 32; s >= 0 && cum < 1.f; --s, ++k) {
        float Ss = sS[s];
        float c2 = fminf(Ss, 1.f - cum);
        if (lane == 0) bcrow[k] = c2;
        cum += Ss;
      }
      nb = k;
    }

    if (lane == 0) g_nb[t * B_DIM + b] = nb;
    P = Pn;
  }
}

// ---------------------------------------------------------------------------
// Kernel B: banded read. One block per (t,b), 64 threads x float4 over E.
// Coefficient loads are warp-uniform (broadcast); zero coeffs skip the v row.
// ---------------------------------------------------------------------------
__global__ __launch_bounds__(64) void read_kernel(
    const float* __restrict__ v, float* __restrict__ out) {
  const int t  = blockIdx.x;
  const int b  = blockIdx.y;
  const int e4 = threadIdx.x;                 // 64 threads * 4 floats = 256

  const int nb = g_nb[t * B_DIM + b];
  const float* __restrict__ bcrow = &g_bc[((size_t)t * B_DIM + b) * KMAX];

  const float4* __restrict__ vb =
      (const float4*)(v + (size_t)b * E_DIM) + e4;
  const size_t row4 = (size_t)B_DIM * E_DIM / 4;

  float4 acc = make_float4(0.f, 0.f, 0.f, 0.f);
  for (int k = 0; k < nb; ++k) {
    float c = __ldg(&bcrow[k]);
    if (c != 0.f) {
      float4 vv = vb[(size_t)(t - k) * row4];
      acc.x = fmaf(c, vv.x, acc.x);
      acc.y = fmaf(c, vv.y, acc.y);
      acc.z = fmaf(c, vv.z, acc.z);
      acc.w = fmaf(c, vv.w, acc.w);
    }
  }
  ((float4*)out)[((size_t)t * B_DIM + b) * (E_DIM / 4) + e4] = acc;
}

// ---------------------------------------------------------------------------
// Inputs: v [T,B,E] f32, u [T,B] f32, d [T,B] f32. Output: reads [T,B,E] f32.
// ---------------------------------------------------------------------------
extern "C" void kernel_launch(void* const* d_in, const int* in_sizes, int n_in,
                              void* d_out, int out_size) {
  const float* v = (const float*)d_in[0];
  const float* u = (const float*)d_in[1];
  const float* d = (const float*)d_in[2];
  float* out = (float*)d_out;

  scan_kernel<<<B_DIM, 32>>>(u, d);

  dim3 grid(T_DIM, B_DIM);
  read_kernel<<<grid, 64>>>(v, out);
}

// round 4
// speedup vs baseline: 5.9250x; 5.9250x over previous
#include <cuda_runtime.h>
#include <cuda_bf16.h>

#define T_DIM 512
#define B_DIM 128
#define E_DIM 256

// Per-batch transposed scratch: Cp[b][t] = prefix sum of (d-u), M[b][t] = d_t - Cp_t.
__device__ float g_Cp[B_DIM * T_DIM];
__device__ float g_M [B_DIM * T_DIM];

// ---------------------------------------------------------------------------
// Kernel 1: per-batch inclusive prefix sum of c_t = d_t - u_t (Hillis-Steele).
// One block per batch, 512 threads. Tiny (~µs).
// ---------------------------------------------------------------------------
__global__ __launch_bounds__(T_DIM) void prefix_kernel(
    const float* __restrict__ u, const float* __restrict__ d) {
  const int b   = blockIdx.x;
  const int tid = threadIdx.x;

  __shared__ float s[T_DIM];
  const float dt = d[tid * B_DIM + b];
  const float ct = dt - u[tid * B_DIM + b];
  s[tid] = ct;
  __syncthreads();

  #pragma unroll
  for (int off = 1; off < T_DIM; off <<= 1) {
    float o = (tid >= off) ? s[tid - off] : 0.f;
    __syncthreads();
    s[tid] += o;
    __syncthreads();
  }

  const float Cp = s[tid];
  g_Cp[b * T_DIM + tid] = Cp;
  g_M [b * T_DIM + tid] = dt - Cp;   // M_t = d_t - Cp_t
}

// ---------------------------------------------------------------------------
// Kernel 2: fused coefficient walk + banded read. One block per (t,b),
// 64 threads x float4 over E. Exact closed form:
//   P_t(i)  = Cp_t + max_{j=t-i..t} M_j      (backward running max)
//   coeff_i = min(P_t(i),1) - min(P_t(i-1),1)
// Walk j downward; running max is monotone so once pc hits 1 all deeper
// coefficients are exactly 0 -> break. All walk values are warp-uniform.
// ---------------------------------------------------------------------------
__global__ __launch_bounds__(64) void read_kernel(
    const float* __restrict__ v, float* __restrict__ out) {
  const int t  = blockIdx.x;
  const int b  = blockIdx.y;
  const int e4 = threadIdx.x;                 // 64 threads * 4 floats = 256

  const float Cpt = __ldg(&g_Cp[b * T_DIM + t]);
  const float* __restrict__ Mb = &g_M[b * T_DIM];

  const float4* __restrict__ vb =
      (const float4*)(v + (size_t)b * E_DIM) + e4;
  const size_t row4 = (size_t)B_DIM * E_DIM / 4;

  float4 acc  = make_float4(0.f, 0.f, 0.f, 0.f);
  float  rm   = -3.4e38f;
  float  prev = 0.f;

  #pragma unroll 1
  for (int j = t; j >= 0; --j) {
    rm = fmaxf(rm, __ldg(&Mb[j]));
    const float pc = fminf(Cpt + rm, 1.f);    // min(P, 1), nondecreasing
    const float c  = pc - prev;
    prev = pc;
    if (c > 0.f) {
      const float4 vv = vb[(size_t)j * row4];
      acc.x = fmaf(c, vv.x, acc.x);
      acc.y = fmaf(c, vv.y, acc.y);
      acc.z = fmaf(c, vv.z, acc.z);
      acc.w = fmaf(c, vv.w, acc.w);
    }
    if (pc >= 1.f) break;                     // all deeper coeffs exactly 0
  }

  ((float4*)out)[((size_t)t * B_DIM + b) * (E_DIM / 4) + e4] = acc;
}

// ---------------------------------------------------------------------------
// Inputs: v [T,B,E] f32, u [T,B] f32, d [T,B] f32. Output: reads [T,B,E] f32.
// ---------------------------------------------------------------------------
extern "C" void kernel_launch(void* const* d_in, const int* in_sizes, int n_in,
                              void* d_out, int out_size) {
  const float* v = (const float*)d_in[0];
  const float* u = (const float*)d_in[1];
  const float* d = (const float*)d_in[2];
  float* out = (float*)d_out;

  prefix_kernel<<<B_DIM, T_DIM>>>(u, d);

  dim3 grid(T_DIM, B_DIM);
  read_kernel<<<grid, 64>>>(v, out);
}